// round 13
// baseline (speedup 1.0000x reference)
#include <cuda_runtime.h>
#include <cuda_bf16.h>
#include <math.h>

// Problem constants
#define NN 100000
#define EE 1600000
#define KDIM 128
#define HF 64          // HEADS * OUT_FEAT
#define NHEADS 4
#define ALPHA 0.2f

// ---------------- scratch (device globals; no allocation allowed) ----------
__device__ float g_h[NN * HF];          // 25.6 MB
__device__ float g_att_src[NN * NHEADS];
__device__ float g_att_dst[NN * NHEADS];
__device__ int   g_deg[NN];
__device__ int   g_off[NN + 1];
__device__ int   g_cursor[NN];
__device__ int   g_csr[EE];
__device__ int   g_bsum[128];
__device__ int   g_is64;                // 1 if edge_index is int64-laid-out

// ---------------- K0: zero degree histogram + detect edge dtype ------------
__global__ void init_kernel(const int* __restrict__ ew) {
    int i = blockIdx.x * blockDim.x + threadIdx.x;
    if (i < NN) g_deg[i] = 0;
    if (blockIdx.x == 0) {
        __shared__ int s_any;
        if (threadIdx.x == 0) s_any = 0;
        __syncthreads();
        int v = ew[2 * (threadIdx.x * 997 + 1) + 1];   // sample odd words
        unsigned nz = __ballot_sync(0xFFFFFFFFu, v != 0);
        if (nz && (threadIdx.x & 31) == 0) atomicOr(&s_any, 1);
        __syncthreads();
        if (threadIdx.x == 0) g_is64 = s_any ? 0 : 1;
    }
}

// ---------------- K1: tensor-core GEMM via mma.sync (bf16 3-term split) ----
// Baseline PTX mma (compiles under compute_103; no tcgen05 needed).
// CTA = 64 rows, 4 warps; warp w owns rows w*16..w*16+15, all 64 cols.
// D[m,n] = sum_k A[m,k]*B[n,k],  A = x tile (split hi/lo), B[n,k] = W[k,n].
#define GPITCH 136              // halfword row pitch (68 words -> conflict-free)
#define SM_AH 0                 // 64*136 halfwords
#define SM_AL (64 * GPITCH)
#define SM_BH (2 * 64 * GPITCH)
#define SM_BL (3 * 64 * GPITCH)
#define SM_HW (4 * 64 * GPITCH)            // total halfwords
#define SM_BYTES (SM_HW * 2)               // 69632 B

__device__ __forceinline__ void mma16816(float* c,
                                         unsigned a0, unsigned a1,
                                         unsigned a2, unsigned a3,
                                         unsigned b0, unsigned b1) {
    asm volatile(
        "mma.sync.aligned.m16n8k16.row.col.f32.bf16.bf16.f32 "
        "{%0,%1,%2,%3}, {%4,%5,%6,%7}, {%8,%9}, {%0,%1,%2,%3};"
        : "+f"(c[0]), "+f"(c[1]), "+f"(c[2]), "+f"(c[3])
        : "r"(a0), "r"(a1), "r"(a2), "r"(a3), "r"(b0), "r"(b1));
}

__global__ __launch_bounds__(128) void gemm_mma_kernel(const float* __restrict__ X,
                                                       const float* __restrict__ W,
                                                       const float* __restrict__ Asrc,
                                                       const float* __restrict__ Adst) {
    extern __shared__ __nv_bfloat16 sm[];
    __nv_bfloat16* Ah = sm + SM_AH;
    __nv_bfloat16* Al = sm + SM_AL;
    __nv_bfloat16* Bh = sm + SM_BH;
    __nv_bfloat16* Bl = sm + SM_BL;

    const int tid  = threadIdx.x;
    const int lane = tid & 31;
    const int wid  = tid >> 5;          // 0..3
    const int row0 = blockIdx.x * 64;

    // Load + split W -> Bh/Bl, stored [n][k] (col-major K x N) so that
    // (k,k+1) pairs are contiguous 32-bit words. W reads are coalesced.
    for (int idx = tid; idx < HF * KDIM; idx += 128) {
        int k = idx >> 6, n = idx & 63;
        float w = W[idx];
        __nv_bfloat16 hi = __float2bfloat16(w);
        __nv_bfloat16 lo = __float2bfloat16(w - __bfloat162float(hi));
        Bh[n * GPITCH + k] = hi;
        Bl[n * GPITCH + k] = lo;
    }
    // Load + split X tile -> Ah/Al, stored [r][k] row-major. Coalesced.
    for (int idx = tid; idx < 64 * KDIM; idx += 128) {
        int r = idx >> 7, k = idx & 127;
        int gr = row0 + r;
        float v = (gr < NN) ? X[(long)gr * KDIM + k] : 0.0f;
        __nv_bfloat16 hi = __float2bfloat16(v);
        __nv_bfloat16 lo = __float2bfloat16(v - __bfloat162float(hi));
        Ah[r * GPITCH + k] = hi;
        Al[r * GPITCH + k] = lo;
    }
    __syncthreads();

    const int qr = lane >> 2;   // 0..7
    const int qc = lane & 3;    // 0..3
    const int r0 = wid * 16;

    float acc[8][4];
#pragma unroll
    for (int j = 0; j < 8; j++)
#pragma unroll
        for (int t = 0; t < 4; t++) acc[j][t] = 0.0f;

#pragma unroll
    for (int s = 0; s < 8; s++) {
        const int ka = 16 * s + qc * 2;
        // A fragments (m16n8k16 row-major): rows r0+qr / r0+qr+8, k pairs ka / ka+8
        unsigned a0h = *(const unsigned*)&Ah[(r0 + qr) * GPITCH + ka];
        unsigned a1h = *(const unsigned*)&Ah[(r0 + qr + 8) * GPITCH + ka];
        unsigned a2h = *(const unsigned*)&Ah[(r0 + qr) * GPITCH + ka + 8];
        unsigned a3h = *(const unsigned*)&Ah[(r0 + qr + 8) * GPITCH + ka + 8];
        unsigned a0l = *(const unsigned*)&Al[(r0 + qr) * GPITCH + ka];
        unsigned a1l = *(const unsigned*)&Al[(r0 + qr + 8) * GPITCH + ka];
        unsigned a2l = *(const unsigned*)&Al[(r0 + qr) * GPITCH + ka + 8];
        unsigned a3l = *(const unsigned*)&Al[(r0 + qr + 8) * GPITCH + ka + 8];
#pragma unroll
        for (int j = 0; j < 8; j++) {
            const int n = j * 8 + qr;
            unsigned b0h = *(const unsigned*)&Bh[n * GPITCH + ka];
            unsigned b1h = *(const unsigned*)&Bh[n * GPITCH + ka + 8];
            unsigned b0l = *(const unsigned*)&Bl[n * GPITCH + ka];
            unsigned b1l = *(const unsigned*)&Bl[n * GPITCH + ka + 8];
            mma16816(acc[j], a0h, a1h, a2h, a3h, b0h, b1h);   // hi*hi
            mma16816(acc[j], a0h, a1h, a2h, a3h, b0l, b1l);   // hi*lo
            mma16816(acc[j], a0l, a1l, a2l, a3l, b0h, b1h);   // lo*hi
        }
    }

    // ---- epilogue: write h + fused attention logits ----
    const int gr_lo = row0 + r0 + qr;       // row for c0,c1
    const int gr_hi = gr_lo + 8;            // row for c2,c3

#pragma unroll
    for (int j = 0; j < 8; j++) {
        int c = j * 8 + qc * 2;
        if (gr_lo < NN)
            *(float2*)&g_h[(long)gr_lo * HF + c] = make_float2(acc[j][0], acc[j][1]);
        if (gr_hi < NN)
            *(float2*)&g_h[(long)gr_hi * HF + c] = make_float2(acc[j][2], acc[j][3]);
    }

    // attention logits: head h covers n-tiles 2h, 2h+1 (cols 16h..16h+15)
#pragma unroll
    for (int h = 0; h < NHEADS; h++) {
        float psl = 0, pdl = 0, psh = 0, pdh = 0;
#pragma unroll
        for (int jj = 0; jj < 2; jj++) {
            int j = 2 * h + jj;
            int c = j * 8 + qc * 2;
            float s0 = __ldg(&Asrc[c]), s1 = __ldg(&Asrc[c + 1]);
            float d0 = __ldg(&Adst[c]), d1 = __ldg(&Adst[c + 1]);
            psl += acc[j][0] * s0 + acc[j][1] * s1;
            pdl += acc[j][0] * d0 + acc[j][1] * d1;
            psh += acc[j][2] * s0 + acc[j][3] * s1;
            pdh += acc[j][2] * d0 + acc[j][3] * d1;
        }
        // reduce across the 4 lanes of this row-quad (qc bits 0,1)
        psl += __shfl_xor_sync(0xFFFFFFFFu, psl, 1);
        psl += __shfl_xor_sync(0xFFFFFFFFu, psl, 2);
        pdl += __shfl_xor_sync(0xFFFFFFFFu, pdl, 1);
        pdl += __shfl_xor_sync(0xFFFFFFFFu, pdl, 2);
        psh += __shfl_xor_sync(0xFFFFFFFFu, psh, 1);
        psh += __shfl_xor_sync(0xFFFFFFFFu, psh, 2);
        pdh += __shfl_xor_sync(0xFFFFFFFFu, pdh, 1);
        pdh += __shfl_xor_sync(0xFFFFFFFFu, pdh, 2);
        if (qc == 0) {
            if (gr_lo < NN) {
                g_att_src[gr_lo * 4 + h] = psl;
                g_att_dst[gr_lo * 4 + h] = pdl;
            }
            if (gr_hi < NN) {
                g_att_src[gr_hi * 4 + h] = psh;
                g_att_dst[gr_hi * 4 + h] = pdh;
            }
        }
    }
}

// ---------------- K2: dst histogram (reads edge_index directly) ------------
__global__ void hist_kernel(const int* __restrict__ ew) {
    int e = blockIdx.x * blockDim.x + threadIdx.x;
    if (e >= EE) return;
    int d = g_is64 ? ew[2 * EE + 2 * e] : ew[EE + e];
    d = min(max(d, 0), NN - 1);
    atomicAdd(&g_deg[d], 1);
}

// ---------------- K3a: per-1024-block exclusive scan of degrees ------------
__global__ void scanA_kernel() {
    __shared__ int sh[1024];
    int i = blockIdx.x * 1024 + threadIdx.x;
    int v = (i < NN) ? g_deg[i] : 0;
    sh[threadIdx.x] = v;
    __syncthreads();
#pragma unroll
    for (int s = 1; s < 1024; s <<= 1) {
        int t = 0;
        if ((int)threadIdx.x >= s) t = sh[threadIdx.x - s];
        __syncthreads();
        if ((int)threadIdx.x >= s) sh[threadIdx.x] += t;
        __syncthreads();
    }
    if (i < NN) g_off[i] = sh[threadIdx.x] - v;
    if (threadIdx.x == 1023) g_bsum[blockIdx.x] = sh[1023];
}

// ---------------- K3b: fixup (each block redundantly scans the 98 sums) ----
__global__ void scanC_kernel(int nblocks) {
    __shared__ int sb[128];
    const int t = threadIdx.x;
    int v = 0;
    if (t < 128) { v = (t < nblocks) ? g_bsum[t] : 0; sb[t] = v; }
    __syncthreads();
#pragma unroll
    for (int s = 1; s < 128; s <<= 1) {
        int add = 0;
        if (t < 128 && t >= s) add = sb[t - s];
        __syncthreads();
        if (t < 128 && t >= s) sb[t] += add;
        __syncthreads();
    }
    if (t < 128) sb[t] -= v;
    __syncthreads();
    int i = blockIdx.x * blockDim.x + t;
    if (i < NN) {
        int o = g_off[i] + sb[i >> 10];
        g_off[i] = o;
        g_cursor[i] = o;
    }
    if (i == 0) g_off[NN] = EE;
}

// ---------------- K4: scatter edges into CSR (grouped by dst) --------------
__global__ void scatter_kernel(const int* __restrict__ ew) {
    int e = blockIdx.x * blockDim.x + threadIdx.x;
    if (e >= EE) return;
    int s, d;
    if (g_is64) { s = ew[2 * e];  d = ew[2 * EE + 2 * e]; }
    else        { s = ew[e];      d = ew[EE + e]; }
    s = min(max(s, 0), NN - 1);
    d = min(max(d, 0), NN - 1);
    int p = atomicAdd(&g_cursor[d], 1);
    g_csr[p] = s;
}

// ---------------- K5: single-pass softmax + aggregation + ELU --------------
__global__ __launch_bounds__(256) void aggregate_kernel(float* __restrict__ out) {
    int warp = (blockIdx.x * blockDim.x + threadIdx.x) >> 5;
    int lane = threadIdx.x & 31;
    if (warp >= NN) return;
    const int n = warp;
    const int start = g_off[n];
    const int end   = g_off[n + 1];

    const int hh = lane >> 3;
    const float adh = __ldg(&g_att_dst[n * 4 + hh]);

    float acc0 = 0.0f, acc1 = 0.0f, dsum = 0.0f;
    const float2* H2 = (const float2*)g_h;

    int j = start;
    const int n4 = start + ((end - start) & ~3);
    for (; j < n4; j += 4) {
        int s0 = g_csr[j], s1 = g_csr[j + 1], s2 = g_csr[j + 2], s3 = g_csr[j + 3];
        float a0 = __ldg(&g_att_src[s0 * 4 + hh]);
        float a1 = __ldg(&g_att_src[s1 * 4 + hh]);
        float a2 = __ldg(&g_att_src[s2 * 4 + hh]);
        float a3 = __ldg(&g_att_src[s3 * 4 + hh]);
        float2 h0 = __ldg(&H2[(long)s0 * 32 + lane]);
        float2 h1 = __ldg(&H2[(long)s1 * 32 + lane]);
        float2 h2 = __ldg(&H2[(long)s2 * 32 + lane]);
        float2 h3 = __ldg(&H2[(long)s3 * 32 + lane]);
        float e0 = a0 + adh; e0 = (e0 > 0.f) ? e0 : ALPHA * e0;
        float e1 = a1 + adh; e1 = (e1 > 0.f) ? e1 : ALPHA * e1;
        float e2 = a2 + adh; e2 = (e2 > 0.f) ? e2 : ALPHA * e2;
        float e3 = a3 + adh; e3 = (e3 > 0.f) ? e3 : ALPHA * e3;
        float w0 = __expf(e0), w1 = __expf(e1), w2 = __expf(e2), w3 = __expf(e3);
        dsum += (w0 + w1) + (w2 + w3);
        acc0 += w0 * h0.x + w1 * h1.x + w2 * h2.x + w3 * h3.x;
        acc1 += w0 * h0.y + w1 * h1.y + w2 * h2.y + w3 * h3.y;
    }
    for (; j < end; j++) {
        int s = g_csr[j];
        float ash = __ldg(&g_att_src[s * 4 + hh]);
        float e = ash + adh;
        e = (e > 0.f) ? e : ALPHA * e;
        float w = __expf(e);
        dsum += w;
        float2 hv = __ldg(&H2[(long)s * 32 + lane]);
        acc0 += w * hv.x;
        acc1 += w * hv.y;
    }

    float inv = 1.0f / (dsum + 1e-16f);
    float o0 = acc0 * inv, o1 = acc1 * inv;
    o0 = (o0 > 0.f) ? o0 : expm1f(o0);
    o1 = (o1 > 0.f) ? o1 : expm1f(o1);
    *(float2*)&out[(long)n * HF + 2 * lane] = make_float2(o0, o1);
}

// ---------------- launch ----------------------------------------------------
extern "C" void kernel_launch(void* const* d_in, const int* in_sizes, int n_in,
                              void* d_out, int out_size) {
    const float* x     = (const float*)d_in[0];
    const int*   ew    = (const int*)d_in[1];
    const float* W     = (const float*)d_in[2];
    const float* a_src = (const float*)d_in[3];
    const float* a_dst = (const float*)d_in[4];
    float* out = (float*)d_out;

    (void)in_sizes; (void)n_in; (void)out_size;

    static cudaStream_t s2 = 0;
    static cudaEvent_t  evA = 0, evB = 0;
    static int tried = 0;
    if (!tried) {
        tried = 1;
        if (cudaStreamCreateWithFlags(&s2, cudaStreamNonBlocking) != cudaSuccess) s2 = 0;
        if (cudaEventCreateWithFlags(&evA, cudaEventDisableTiming) != cudaSuccess) evA = 0;
        if (cudaEventCreateWithFlags(&evB, cudaEventDisableTiming) != cudaSuccess) evB = 0;
        // opt into >48KB dynamic smem (first call is the uncaptured correctness run)
        cudaFuncSetAttribute(gemm_mma_kernel,
                             cudaFuncAttributeMaxDynamicSharedMemorySize, SM_BYTES);
    }
    const bool overlap = (s2 && evA && evB);

    const int NB = (NN + 1023) / 1024;        // 98
    const int NTILES = (NN + 63) / 64;        // 1563

    init_kernel<<<(NN + 255) / 256, 256>>>(ew);

    if (overlap) {
        cudaEventRecord(evA, 0);
        cudaStreamWaitEvent(s2, evA, 0);
        hist_kernel<<<(EE + 255) / 256, 256, 0, s2>>>(ew);
        scanA_kernel<<<NB, 1024, 0, s2>>>();
        scanC_kernel<<<(NN + 255) / 256, 256, 0, s2>>>(NB);
        scatter_kernel<<<(EE + 255) / 256, 256, 0, s2>>>(ew);
        cudaEventRecord(evB, s2);
        gemm_mma_kernel<<<NTILES, 128, SM_BYTES>>>(x, W, a_src, a_dst);
        cudaStreamWaitEvent(0, evB, 0);
    } else {
        hist_kernel<<<(EE + 255) / 256, 256>>>(ew);
        scanA_kernel<<<NB, 1024>>>();
        scanC_kernel<<<(NN + 255) / 256, 256>>>(NB);
        scatter_kernel<<<(EE + 255) / 256, 256>>>(ew);
        gemm_mma_kernel<<<NTILES, 128, SM_BYTES>>>(x, W, a_src, a_dst);
    }

    aggregate_kernel<<<(NN * 32 + 255) / 256, 256>>>(out);
}

// round 14
// speedup vs baseline: 1.1235x; 1.1235x over previous
#include <cuda_runtime.h>
#include <cuda_fp16.h>
#include <math.h>

// Problem constants
#define NN 100000
#define EE 1600000
#define KDIM 128
#define HF 64          // HEADS * OUT_FEAT
#define NHEADS 4
#define ALPHA 0.2f

// ---------------- scratch (device globals; no allocation allowed) ----------
__device__ __half g_h[NN * HF];         // 12.8 MB (fp16 h; only consumer is aggregate)
__device__ float g_att_src[NN * NHEADS];
__device__ float g_att_dst[NN * NHEADS];
__device__ int   g_deg[NN];
__device__ int   g_off[NN + 1];
__device__ int   g_cursor[NN];
__device__ int   g_csr[EE];
__device__ int   g_bsum[128];
__device__ int   g_is64;                // 1 if edge_index is int64-laid-out

// ---------------- K0: zero degree histogram + detect edge dtype ------------
__global__ void init_kernel(const int* __restrict__ ew) {
    int i = blockIdx.x * blockDim.x + threadIdx.x;
    if (i < NN) g_deg[i] = 0;
    if (blockIdx.x == 0) {
        __shared__ int s_any;
        if (threadIdx.x == 0) s_any = 0;
        __syncthreads();
        int v = ew[2 * (threadIdx.x * 997 + 1) + 1];   // sample odd words
        unsigned nz = __ballot_sync(0xFFFFFFFFu, v != 0);
        if (nz && (threadIdx.x & 31) == 0) atomicOr(&s_any, 1);
        __syncthreads();
        if (threadIdx.x == 0) g_is64 = s_any ? 0 : 1;
    }
}

// ---------------- K1: GEMM  h = x @ W  + fused attention-logit epilogue ----
// R6/R9 measured scalar kernel; only change: h stored as fp16 pairs.
__global__ __launch_bounds__(256) void gemm_kernel(const float* __restrict__ X,
                                                   const float* __restrict__ W,
                                                   const float* __restrict__ Asrc,
                                                   const float* __restrict__ Adst) {
    __shared__ float Xs[32][68];   // [k][row], padded row pitch
    __shared__ float Ws[32][64];   // [k][col]

    const int block_row = blockIdx.x * 64;
    const int tx = threadIdx.x & 15;        // 0..15 -> 4 cols each
    const int ty = threadIdx.x >> 4;        // 0..15 -> 4 rows each
    const int lane = threadIdx.x & 31;
    const int wrp  = threadIdx.x >> 5;      // 0..7

    float acc[4][4];
#pragma unroll
    for (int i = 0; i < 4; i++)
#pragma unroll
        for (int j = 0; j < 4; j++) acc[i][j] = 0.0f;

    for (int k0 = 0; k0 < KDIM; k0 += 32) {
#pragma unroll
        for (int r = 0; r < 8; r++) {
            int row = wrp * 8 + r;
            int gr  = block_row + row;
            float v = 0.0f;
            if (gr < NN) v = X[(long)gr * KDIM + k0 + lane];
            Xs[lane][row] = v;
        }
#pragma unroll
        for (int i = 0; i < 8; i++) {
            int idx = threadIdx.x + i * 256;
            int kk = idx >> 6, cc = idx & 63;
            Ws[kk][cc] = W[(k0 + kk) * HF + cc];
        }
        __syncthreads();

#pragma unroll
        for (int k = 0; k < 32; k++) {
            float4 xv = *(const float4*)&Xs[k][ty * 4];
            float4 wv = *(const float4*)&Ws[k][tx * 4];
            acc[0][0] += xv.x * wv.x; acc[0][1] += xv.x * wv.y;
            acc[0][2] += xv.x * wv.z; acc[0][3] += xv.x * wv.w;
            acc[1][0] += xv.y * wv.x; acc[1][1] += xv.y * wv.y;
            acc[1][2] += xv.y * wv.z; acc[1][3] += xv.y * wv.w;
            acc[2][0] += xv.z * wv.x; acc[2][1] += xv.z * wv.y;
            acc[2][2] += xv.z * wv.z; acc[2][3] += xv.z * wv.w;
            acc[3][0] += xv.w * wv.x; acc[3][1] += xv.w * wv.y;
            acc[3][2] += xv.w * wv.z; acc[3][3] += xv.w * wv.w;
        }
        __syncthreads();
    }

    // epilogue: write h (fp16) + fused attention logits (fp32, exact)
    float as_r[4], ad_r[4];
#pragma unroll
    for (int j = 0; j < 4; j++) {
        as_r[j] = Asrc[tx * 4 + j];
        ad_r[j] = Adst[tx * 4 + j];
    }
    const int head = tx >> 2;   // 0..3

#pragma unroll
    for (int i = 0; i < 4; i++) {
        int gr = block_row + ty * 4 + i;
        float ps = acc[i][0] * as_r[0] + acc[i][1] * as_r[1]
                 + acc[i][2] * as_r[2] + acc[i][3] * as_r[3];
        float pd = acc[i][0] * ad_r[0] + acc[i][1] * ad_r[1]
                 + acc[i][2] * ad_r[2] + acc[i][3] * ad_r[3];
        ps += __shfl_xor_sync(0xFFFFFFFFu, ps, 1);
        ps += __shfl_xor_sync(0xFFFFFFFFu, ps, 2);
        pd += __shfl_xor_sync(0xFFFFFFFFu, pd, 1);
        pd += __shfl_xor_sync(0xFFFFFFFFu, pd, 2);
        if (gr < NN) {
            __half2 p0 = __floats2half2_rn(acc[i][0], acc[i][1]);
            __half2 p1 = __floats2half2_rn(acc[i][2], acc[i][3]);
            uint2 pk;
            pk.x = *(unsigned*)&p0;
            pk.y = *(unsigned*)&p1;
            *(uint2*)&g_h[(long)gr * HF + tx * 4] = pk;   // 8B aligned store
            if ((lane & 3) == 0) {
                g_att_src[gr * 4 + head] = ps;
                g_att_dst[gr * 4 + head] = pd;
            }
        }
    }
}

// ---------------- K2: dst histogram (reads edge_index directly) ------------
__global__ void hist_kernel(const int* __restrict__ ew) {
    int e = blockIdx.x * blockDim.x + threadIdx.x;
    if (e >= EE) return;
    int d = g_is64 ? ew[2 * EE + 2 * e] : ew[EE + e];
    d = min(max(d, 0), NN - 1);
    atomicAdd(&g_deg[d], 1);
}

// ---------------- K3a: per-1024-block exclusive scan of degrees ------------
__global__ void scanA_kernel() {
    __shared__ int sh[1024];
    int i = blockIdx.x * 1024 + threadIdx.x;
    int v = (i < NN) ? g_deg[i] : 0;
    sh[threadIdx.x] = v;
    __syncthreads();
#pragma unroll
    for (int s = 1; s < 1024; s <<= 1) {
        int t = 0;
        if ((int)threadIdx.x >= s) t = sh[threadIdx.x - s];
        __syncthreads();
        if ((int)threadIdx.x >= s) sh[threadIdx.x] += t;
        __syncthreads();
    }
    if (i < NN) g_off[i] = sh[threadIdx.x] - v;
    if (threadIdx.x == 1023) g_bsum[blockIdx.x] = sh[1023];
}

// ---------------- K3b: fixup (each block redundantly scans the 98 sums) ----
__global__ void scanC_kernel(int nblocks) {
    __shared__ int sb[128];
    const int t = threadIdx.x;
    int v = 0;
    if (t < 128) { v = (t < nblocks) ? g_bsum[t] : 0; sb[t] = v; }
    __syncthreads();
#pragma unroll
    for (int s = 1; s < 128; s <<= 1) {
        int add = 0;
        if (t < 128 && t >= s) add = sb[t - s];
        __syncthreads();
        if (t < 128 && t >= s) sb[t] += add;
        __syncthreads();
    }
    if (t < 128) sb[t] -= v;
    __syncthreads();
    int i = blockIdx.x * blockDim.x + t;
    if (i < NN) {
        int o = g_off[i] + sb[i >> 10];
        g_off[i] = o;
        g_cursor[i] = o;
    }
    if (i == 0) g_off[NN] = EE;
}

// ---------------- K4: scatter edges into CSR (grouped by dst) --------------
__global__ void scatter_kernel(const int* __restrict__ ew) {
    int e = blockIdx.x * blockDim.x + threadIdx.x;
    if (e >= EE) return;
    int s, d;
    if (g_is64) { s = ew[2 * e];  d = ew[2 * EE + 2 * e]; }
    else        { s = ew[e];      d = ew[EE + e]; }
    s = min(max(s, 0), NN - 1);
    d = min(max(d, 0), NN - 1);
    int p = atomicAdd(&g_cursor[d], 1);
    g_csr[p] = s;
}

// ---------------- K5: single-pass softmax + aggregation + ELU --------------
// One warp per destination node; h gathered as fp16 pairs (4B/lane/edge).
__global__ __launch_bounds__(256) void aggregate_kernel(float* __restrict__ out) {
    int warp = (blockIdx.x * blockDim.x + threadIdx.x) >> 5;
    int lane = threadIdx.x & 31;
    if (warp >= NN) return;
    const int n = warp;
    const int start = g_off[n];
    const int end   = g_off[n + 1];

    const int hh = lane >> 3;
    const float adh = __ldg(&g_att_dst[n * 4 + hh]);

    float acc0 = 0.0f, acc1 = 0.0f, dsum = 0.0f;
    const unsigned* H2 = (const unsigned*)g_h;   // one __half2 (2 feats) per lane

    int j = start;
    const int n4 = start + ((end - start) & ~3);
    for (; j < n4; j += 4) {
        int s0 = g_csr[j], s1 = g_csr[j + 1], s2 = g_csr[j + 2], s3 = g_csr[j + 3];
        float a0 = __ldg(&g_att_src[s0 * 4 + hh]);
        float a1 = __ldg(&g_att_src[s1 * 4 + hh]);
        float a2 = __ldg(&g_att_src[s2 * 4 + hh]);
        float a3 = __ldg(&g_att_src[s3 * 4 + hh]);
        unsigned u0 = __ldg(&H2[(long)s0 * 32 + lane]);
        unsigned u1 = __ldg(&H2[(long)s1 * 32 + lane]);
        unsigned u2 = __ldg(&H2[(long)s2 * 32 + lane]);
        unsigned u3 = __ldg(&H2[(long)s3 * 32 + lane]);
        float e0 = a0 + adh; e0 = (e0 > 0.f) ? e0 : ALPHA * e0;
        float e1 = a1 + adh; e1 = (e1 > 0.f) ? e1 : ALPHA * e1;
        float e2 = a2 + adh; e2 = (e2 > 0.f) ? e2 : ALPHA * e2;
        float e3 = a3 + adh; e3 = (e3 > 0.f) ? e3 : ALPHA * e3;
        float w0 = __expf(e0), w1 = __expf(e1), w2 = __expf(e2), w3 = __expf(e3);
        dsum += (w0 + w1) + (w2 + w3);
        float2 h0 = __half22float2(*(__half2*)&u0);
        float2 h1 = __half22float2(*(__half2*)&u1);
        float2 h2 = __half22float2(*(__half2*)&u2);
        float2 h3 = __half22float2(*(__half2*)&u3);
        acc0 += w0 * h0.x + w1 * h1.x + w2 * h2.x + w3 * h3.x;
        acc1 += w0 * h0.y + w1 * h1.y + w2 * h2.y + w3 * h3.y;
    }
    for (; j < end; j++) {
        int s = g_csr[j];
        float ash = __ldg(&g_att_src[s * 4 + hh]);
        float e = ash + adh;
        e = (e > 0.f) ? e : ALPHA * e;
        float w = __expf(e);
        dsum += w;
        unsigned u = __ldg(&H2[(long)s * 32 + lane]);
        float2 hv = __half22float2(*(__half2*)&u);
        acc0 += w * hv.x;
        acc1 += w * hv.y;
    }

    float inv = 1.0f / (dsum + 1e-16f);
    float o0 = acc0 * inv, o1 = acc1 * inv;
    o0 = (o0 > 0.f) ? o0 : expm1f(o0);
    o1 = (o1 > 0.f) ? o1 : expm1f(o1);
    *(float2*)&out[(long)n * HF + 2 * lane] = make_float2(o0, o1);
}

// ---------------- launch ----------------------------------------------------
extern "C" void kernel_launch(void* const* d_in, const int* in_sizes, int n_in,
                              void* d_out, int out_size) {
    const float* x     = (const float*)d_in[0];
    const int*   ew    = (const int*)d_in[1];
    const float* W     = (const float*)d_in[2];
    const float* a_src = (const float*)d_in[3];
    const float* a_dst = (const float*)d_in[4];
    float* out = (float*)d_out;

    (void)in_sizes; (void)n_in; (void)out_size;

    static cudaStream_t s2 = 0;
    static cudaEvent_t  evA = 0, evB = 0;
    static int tried = 0;
    if (!tried) {
        tried = 1;
        if (cudaStreamCreateWithFlags(&s2, cudaStreamNonBlocking) != cudaSuccess) s2 = 0;
        if (cudaEventCreateWithFlags(&evA, cudaEventDisableTiming) != cudaSuccess) evA = 0;
        if (cudaEventCreateWithFlags(&evB, cudaEventDisableTiming) != cudaSuccess) evB = 0;
    }
    const bool overlap = (s2 && evA && evB);

    const int NB = (NN + 1023) / 1024;   // 98

    init_kernel<<<(NN + 255) / 256, 256>>>(ew);

    if (overlap) {
        cudaEventRecord(evA, 0);
        cudaStreamWaitEvent(s2, evA, 0);
        hist_kernel<<<(EE + 255) / 256, 256, 0, s2>>>(ew);
        scanA_kernel<<<NB, 1024, 0, s2>>>();
        scanC_kernel<<<(NN + 255) / 256, 256, 0, s2>>>(NB);
        scatter_kernel<<<(EE + 255) / 256, 256, 0, s2>>>(ew);
        cudaEventRecord(evB, s2);
        gemm_kernel<<<(NN + 63) / 64, 256>>>(x, W, a_src, a_dst);
        cudaStreamWaitEvent(0, evB, 0);
    } else {
        hist_kernel<<<(EE + 255) / 256, 256>>>(ew);
        scanA_kernel<<<NB, 1024>>>();
        scanC_kernel<<<(NN + 255) / 256, 256>>>(NB);
        scatter_kernel<<<(EE + 255) / 256, 256>>>(ew);
        gemm_kernel<<<(NN + 63) / 64, 256>>>(x, W, a_src, a_dst);
    }

    aggregate_kernel<<<(NN * 32 + 255) / 256, 256>>>(out);
}